// round 9
// baseline (speedup 1.0000x reference)
#include <cuda_runtime.h>
#include <cuda_bf16.h>
#include <math.h>
#include <stdint.h>

// ============================================================================
// CTC decoder, round 9: FP8 GEMM with FIXED cp.async lookahead (wait_group 2).
//   K1 prep     : out=LOGZERO, g_sumexp=0, x->e4m3, W*64->e4m3
//   K2 gemm_mma : 128x128x128 fp8 m16n8k32, 3-stage ring, true 2-chunk
//                 lookahead, fused exp-sum + beam extraction
//   K3 scan     : per-batch CTC recursion from smem
// ============================================================================

#define LOGZERO (-4290774016.0f)
#define WSCALE     64.0f
#define INV_WSCALE 0.015625f

__device__ float g_sumexp[32768];
__device__ float g_blank[32768];
__device__ float g_beam[32768 * 32];
__device__ __align__(16) uint8_t g_x8[16384 * 512];
__device__ __align__(16) uint8_t g_w8[4096 * 512];

// ---------------------------------------------------------------- helpers
__device__ __forceinline__ uint32_t smem_u32(const void* p) {
    uint32_t a;
    asm("{ .reg .u64 t; cvta.to.shared.u64 t, %1; cvt.u32.u64 %0, t; }"
        : "=r"(a) : "l"(p));
    return a;
}
#define CP_ASYNC16(dst, src) \
    asm volatile("cp.async.cg.shared.global [%0], [%1], 16;" :: "r"(dst), "l"(src))
#define CP_COMMIT() asm volatile("cp.async.commit_group;" ::: "memory")
#define CP_WAIT(n)  asm volatile("cp.async.wait_group %0;" :: "n"(n) : "memory")

__device__ __forceinline__ void ldmatrix_x4(uint32_t& r0, uint32_t& r1,
                                            uint32_t& r2, uint32_t& r3, uint32_t a) {
    asm volatile("ldmatrix.sync.aligned.m8n8.x4.shared.b16 {%0,%1,%2,%3}, [%4];"
                 : "=r"(r0), "=r"(r1), "=r"(r2), "=r"(r3) : "r"(a));
}
__device__ __forceinline__ void mma_e4m3(float* c, const uint32_t* a, const uint32_t* b) {
    asm volatile(
        "mma.sync.aligned.m16n8k32.row.col.f32.e4m3.e4m3.f32 "
        "{%0,%1,%2,%3}, {%4,%5,%6,%7}, {%8,%9}, {%0,%1,%2,%3};"
        : "+f"(c[0]), "+f"(c[1]), "+f"(c[2]), "+f"(c[3])
        : "r"(a[0]), "r"(a[1]), "r"(a[2]), "r"(a[3]), "r"(b[0]), "r"(b[1]));
}
__device__ __forceinline__ uint32_t pack_e4m3_4(float a, float b, float c, float d) {
    uint16_t lo, hi;
    asm("cvt.rn.satfinite.e4m3x2.f32 %0, %1, %2;" : "=h"(lo) : "f"(b), "f"(a));
    asm("cvt.rn.satfinite.e4m3x2.f32 %0, %1, %2;" : "=h"(hi) : "f"(d), "f"(c));
    return (uint32_t)lo | ((uint32_t)hi << 16);
}

__device__ __forceinline__ float laexp(float a, float b) {
    float m = fmaxf(a, b);
    float d = fminf(a, b) - m;
    return m + __logf(1.0f + __expf(d));
}

// ---------------------------------------------------------------- K1: prep
__global__ void prep_kernel(const float* __restrict__ x, const float* __restrict__ W,
                            float* __restrict__ out, int nx, int nw, int outN, int M) {
    int idx = blockIdx.x * blockDim.x + threadIdx.x;
    if (idx < outN) out[idx] = LOGZERO;
    if (idx < M)    g_sumexp[idx] = 0.0f;
    int i4 = idx << 2;
    if (i4 < nx) {
        float4 v = *reinterpret_cast<const float4*>(x + i4);
        *reinterpret_cast<uint32_t*>(g_x8 + i4) = pack_e4m3_4(v.x, v.y, v.z, v.w);
    } else {
        int j4 = i4 - nx;
        if (j4 < nw) {
            float4 v = *reinterpret_cast<const float4*>(W + j4);
            *reinterpret_cast<uint32_t*>(g_w8 + j4) =
                pack_e4m3_4(v.x * WSCALE, v.y * WSCALE, v.z * WSCALE, v.w * WSCALE);
        }
    }
}

// ---------------------------------------------------------------- K2: GEMM
#define BM 128
#define BN 128
#define BKB 128                          // fp8 bytes per chunk
#define STRIDE 144                       // smem row bytes (conflict-free)
#define OPB    (BM * STRIDE)             // 18432 B per operand per stage
#define STAGE_B (2 * OPB)                // 36864 B per stage
#define NSTAGE 3
#define SM_BIAS (NSTAGE * STAGE_B)
#define SM_SLOT (SM_BIAS + 512)
#define SM_TOTAL (SM_SLOT + 512)

__global__ __launch_bounds__(256, 2)
void gemm_mma_kernel(const float* __restrict__ bias,
                     const int* __restrict__ beam, const int* __restrict__ blankp,
                     int M, int N, int K, int T, int CB) {
    extern __shared__ __align__(16) char smem[];
    float* sbias = reinterpret_cast<float*>(smem + SM_BIAS);
    int*   sslot = reinterpret_cast<int*>(smem + SM_SLOT);

    const int tid  = threadIdx.x;
    const int lane = tid & 31;
    const int wid  = tid >> 5;
    const int wm   = wid & 3;
    const int wn   = wid >> 2;
    const int bm   = blockIdx.y << 7;
    const int bn   = blockIdx.x << 7;
    const int bcta = bm / T;

    if (tid < BN) {
        sbias[tid] = bias[bn + tid];
        sslot[tid] = -1;
    }
    __syncthreads();
    if (tid <= CB) {
        int col = (tid < CB) ? beam[bcta * CB + tid] : (blankp ? blankp[0] : 0);
        if ((unsigned)(col - bn) < (unsigned)BN) sslot[col - bn] = tid;  // CB = blank
    }

    const int l_row = tid >> 3;              // 0..31
    const int l_cb  = (tid & 7) << 4;        // byte col 0..112
    const uint8_t* gA = g_x8 + (size_t)(bm + l_row) * K + l_cb;
    const uint8_t* gB = g_w8 + (size_t)(bn + l_row) * K + l_cb;

    const uint32_t sm_u32 = smem_u32(smem);
    const uint32_t dA = sm_u32 + (uint32_t)(l_row * STRIDE + l_cb);
    const uint32_t dB = dA + OPB;
    const size_t gp = (size_t)32 * K;
    const uint32_t sp = 32 * STRIDE;

    const int NC = K >> 7;                   // 4 chunks of 128

    // prologue: issue chunks 0,1 into stages 0,1
#pragma unroll
    for (int c = 0; c < 2; c++) {
        if (c < NC) {
            uint32_t sb = (uint32_t)c * STAGE_B;
            const uint8_t* a = gA + (size_t)c * BKB;
            const uint8_t* b = gB + (size_t)c * BKB;
#pragma unroll
            for (int p = 0; p < 4; p++) {
                CP_ASYNC16(dA + sb + p * sp, a + p * gp);
                CP_ASYNC16(dB + sb + p * sp, b + p * gp);
            }
        }
        CP_COMMIT();
    }

    float acc[2][8][4];
#pragma unroll
    for (int mt = 0; mt < 2; mt++)
#pragma unroll
        for (int nt = 0; nt < 8; nt++)
#pragma unroll
            for (int i = 0; i < 4; i++) acc[mt][nt][i] = 0.0f;

    const int a_row  = wm * 32 + (lane & 15);
    const int a_koff = (lane >> 4) << 4;
    const int b_row  = wn * 64 + ((lane >> 4) << 3) + (lane & 7);
    const int b_koff = ((lane >> 3) & 1) << 4;

    int s_cur = 0, s_nxt2 = 2;
    for (int c = 0; c < NC; c++) {
        __syncthreads();            // all warps done reading stage s_nxt2

        if (c + 2 < NC) {           // issue chunk c+2 post-barrier: race-free
            uint32_t sb = (uint32_t)s_nxt2 * STAGE_B;
            const uint8_t* a = gA + (size_t)(c + 2) * BKB;
            const uint8_t* b = gB + (size_t)(c + 2) * BKB;
#pragma unroll
            for (int p = 0; p < 4; p++) {
                CP_ASYNC16(dA + sb + p * sp, a + p * gp);
                CP_ASYNC16(dB + sb + p * sp, b + p * gp);
            }
        }
        CP_COMMIT();

        CP_WAIT(2);                 // chunk c resident; c+1, c+2 stay in flight
        __syncthreads();            // cp.async visibility across warps

        const uint32_t abase = sm_u32 + (uint32_t)s_cur * STAGE_B;
        const uint32_t bbase = abase + OPB;

#pragma unroll
        for (int kt = 0; kt < 4; kt++) {
            uint32_t af[2][4];
#pragma unroll
            for (int mt = 0; mt < 2; mt++) {
                uint32_t addr = abase +
                    (uint32_t)((a_row + mt * 16) * STRIDE + kt * 32 + a_koff);
                ldmatrix_x4(af[mt][0], af[mt][1], af[mt][2], af[mt][3], addr);
            }
            uint32_t bf[8][2];
#pragma unroll
            for (int nt2 = 0; nt2 < 4; nt2++) {
                uint32_t addr = bbase +
                    (uint32_t)((b_row + nt2 * 16) * STRIDE + kt * 32 + b_koff);
                uint32_t r0, r1, r2, r3;
                ldmatrix_x4(r0, r1, r2, r3, addr);
                bf[nt2 * 2][0] = r0;      bf[nt2 * 2][1] = r1;
                bf[nt2 * 2 + 1][0] = r2;  bf[nt2 * 2 + 1][1] = r3;
            }
#pragma unroll
            for (int mt = 0; mt < 2; mt++)
#pragma unroll
                for (int nt = 0; nt < 8; nt++)
                    mma_e4m3(acc[mt][nt], af[mt], bf[nt]);
        }

        if (++s_cur == NSTAGE) s_cur = 0;
        if (++s_nxt2 == NSTAGE) s_nxt2 = 0;
    }

    // epilogue: rescale + bias, exp-sum, slot scatter
    const int gq = lane >> 2;
    const int qc = (lane & 3) << 1;
#pragma unroll
    for (int mt = 0; mt < 2; mt++) {
        const int r0 = bm + wm * 32 + mt * 16 + gq;
        float s0 = 0.0f, s1 = 0.0f;
#pragma unroll
        for (int nt = 0; nt < 8; nt++) {
            const int c0 = wn * 64 + nt * 8 + qc;
            float b0 = sbias[c0];
            float b1 = sbias[c0 + 1];
            float v00 = fmaf(acc[mt][nt][0], INV_WSCALE, b0);
            float v01 = fmaf(acc[mt][nt][1], INV_WSCALE, b1);
            float v10 = fmaf(acc[mt][nt][2], INV_WSCALE, b0);
            float v11 = fmaf(acc[mt][nt][3], INV_WSCALE, b1);
            s0 += __expf(v00) + __expf(v01);
            s1 += __expf(v10) + __expf(v11);
            int sl0 = sslot[c0], sl1 = sslot[c0 + 1];
            if (sl0 >= 0) {
                if (sl0 == CB) { g_blank[r0] = v00; g_blank[r0 + 8] = v10; }
                else { g_beam[(size_t)r0 * CB + sl0] = v00;
                       g_beam[(size_t)(r0 + 8) * CB + sl0] = v10; }
            }
            if (sl1 >= 0) {
                if (sl1 == CB) { g_blank[r0] = v01; g_blank[r0 + 8] = v11; }
                else { g_beam[(size_t)r0 * CB + sl1] = v01;
                       g_beam[(size_t)(r0 + 8) * CB + sl1] = v11; }
            }
        }
        s0 += __shfl_xor_sync(0xffffffffu, s0, 1);
        s0 += __shfl_xor_sync(0xffffffffu, s0, 2);
        s1 += __shfl_xor_sync(0xffffffffu, s1, 1);
        s1 += __shfl_xor_sync(0xffffffffu, s1, 2);
        if ((lane & 3) == 0) {
            atomicAdd(&g_sumexp[r0], s0);
            atomicAdd(&g_sumexp[r0 + 8], s1);
        }
    }
}

// ---------------------------------------------------------------- K3: scan
__global__ void scan_kernel(const int* __restrict__ xl, const int* __restrict__ beam,
                            const int* __restrict__ blankp, const int* __restrict__ eosp,
                            float* __restrict__ out, int T, int V, int CB, int Ly) {
    extern __shared__ float dsm[];
    float* s_lse = dsm;
    float* s_lpb = dsm + T;
    float* s_xn  = dsm + 2 * T;

    const int b = blockIdx.x;
    const int tid = threadIdx.x;
    const int blankv = blankp ? blankp[0] : 0;
    const int eosv   = eosp ? eosp[0] : (V - 1);
    const int xlb = xl[b];

    for (int t = tid; t < T; t += blockDim.x) {
        float lse = __logf(g_sumexp[b * T + t]);
        s_lse[t] = lse;
        s_lpb[t] = g_blank[b * T + t] - lse;
    }
    __syncthreads();
    for (int idx = tid; idx < T * CB; idx += blockDim.x) {
        int t = idx / CB, j = idx - t * CB;
        s_xn[t * 32 + j] = g_beam[(size_t)(b * T + t) * CB + j] - s_lse[t];
    }
    __syncthreads();

    if (tid < 32) {
        const int j = tid;
        const bool active = (j < CB);
        int start = Ly < (T - 1) ? Ly : (T - 1);
        int loop_start = start > 1 ? start : 1;

        float Pn = LOGZERO, Pb = LOGZERO, acc = LOGZERO;
        float cum = 0.0f, pref = 0.0f, eosval = 0.0f;

        for (int t = 0; t < T; t++) {
            float lpb = s_lpb[t];
            cum = (t == 0) ? lpb : (cum + lpb);
            if (active) {
                float xn = s_xn[t * 32 + j];
                if (t == 0 && start == 0) {
                    Pn = xn; Pb = LOGZERO;
                } else if (t >= loop_start) {
                    float pn = laexp(Pn, pref) + xn;
                    float pb = laexp(Pn, Pb) + lpb;
                    Pn = pn; Pb = pb;
                }
                if (t >= start && t < xlb)
                    acc = laexp(acc, laexp(Pn, Pb));
            }
            if (t == xlb - 1) eosval = cum;
            pref = cum;
        }

        if (active) out[(size_t)b * V + beam[b * CB + j]] = acc;
        __syncwarp();
        if (j == 0) {
            out[(size_t)b * V + eosv]   = (xlb >= 1 && xlb <= T) ? eosval : 0.0f;
            out[(size_t)b * V + blankv] = LOGZERO;
        }
    }
}

// ---------------------------------------------------------------------------
extern "C" void kernel_launch(void* const* d_in, const int* in_sizes, int n_in,
                              void* d_out, int out_size) {
    const float* x    = (const float*)d_in[0];   // (B,T,D)
    const float* W    = (const float*)d_in[1];   // (V,D)
    const float* bias = (const float*)d_in[2];   // (V,)
    const int*   xl   = (const int*)d_in[3];     // (B,)
    // d_in[4] = y : unused (lastPsum == lastP1 in f32, branch collapses)
    const int*   beam = (const int*)d_in[5];     // (B,CB)
    const int*   blankp = (n_in > 6) ? (const int*)d_in[6] : nullptr;
    const int*   eosp   = (n_in > 7) ? (const int*)d_in[7] : nullptr;

    const int B  = in_sizes[3];
    const int V  = in_sizes[2];
    const int D  = in_sizes[1] / V;
    const int T  = in_sizes[0] / (B * D);
    const int CB = in_sizes[5] / B;
    const int Ly = in_sizes[4] / B;
    const int M  = B * T;

    float* out = (float*)d_out;

    const int nx = M * D, nw = V * D;
    int nthr = (nx + nw) >> 2;
    if (nthr < out_size) nthr = out_size;
    prep_kernel<<<(nthr + 255) / 256, 256>>>(x, W, out, nx, nw, out_size, M);

    cudaFuncSetAttribute(gemm_mma_kernel,
                         cudaFuncAttributeMaxDynamicSharedMemorySize, SM_TOTAL);
    dim3 gg(V >> 7, M >> 7);
    gemm_mma_kernel<<<gg, 256, SM_TOTAL>>>(bias, beam, blankp, M, V, D, T, CB);

    int ssm = (2 * T + T * 32) * 4;
    cudaFuncSetAttribute(scan_kernel,
                         cudaFuncAttributeMaxDynamicSharedMemorySize, ssm);
    scan_kernel<<<B, 256, ssm>>>(xl, beam, blankp, eosp, out, T, V, CB, Ly);
}

// round 10
// speedup vs baseline: 1.0629x; 1.0629x over previous
#include <cuda_runtime.h>
#include <cuda_bf16.h>
#include <math.h>
#include <stdint.h>

// ============================================================================
// CTC decoder, round 10: revert to round-7 bf16 GEMM (best: 321.6us) and pad
// the graph to 5 kernels so ncu's fixed capture point lands on gemm_mma.
//   K1 prep     : out=LOGZERO, g_sumexp=0, x/W fp32->bf16
//   D1,D2 dummy : no-op scratch writes (profiler alignment)
//   K2 gemm_mma : 128x128x64 bf16 m16n8k16, 3-stage ring, fused epilogue
//   K3 scan     : per-batch CTC recursion from smem
// ============================================================================

#define LOGZERO (-4290774016.0f)

__device__ float g_sumexp[32768];
__device__ float g_blank[32768];
__device__ float g_beam[32768 * 32];
__device__ int   g_dummy[2];
__device__ __align__(16) __nv_bfloat16 g_xb[16384 * 512];
__device__ __align__(16) __nv_bfloat16 g_wb[4096 * 512];

// ---------------------------------------------------------------- helpers
__device__ __forceinline__ uint32_t smem_u32(const void* p) {
    uint32_t a;
    asm("{ .reg .u64 t; cvta.to.shared.u64 t, %1; cvt.u32.u64 %0, t; }"
        : "=r"(a) : "l"(p));
    return a;
}
#define CP_ASYNC16(dst, src) \
    asm volatile("cp.async.cg.shared.global [%0], [%1], 16;" :: "r"(dst), "l"(src))
#define CP_COMMIT() asm volatile("cp.async.commit_group;" ::: "memory")
#define CP_WAIT(n)  asm volatile("cp.async.wait_group %0;" :: "n"(n) : "memory")

__device__ __forceinline__ void ldmatrix_x4(uint32_t& r0, uint32_t& r1,
                                            uint32_t& r2, uint32_t& r3, uint32_t a) {
    asm volatile("ldmatrix.sync.aligned.m8n8.x4.shared.b16 {%0,%1,%2,%3}, [%4];"
                 : "=r"(r0), "=r"(r1), "=r"(r2), "=r"(r3) : "r"(a));
}
__device__ __forceinline__ void mma_bf16(float* c, const uint32_t* a, const uint32_t* b) {
    asm volatile(
        "mma.sync.aligned.m16n8k16.row.col.f32.bf16.bf16.f32 "
        "{%0,%1,%2,%3}, {%4,%5,%6,%7}, {%8,%9}, {%0,%1,%2,%3};"
        : "+f"(c[0]), "+f"(c[1]), "+f"(c[2]), "+f"(c[3])
        : "r"(a[0]), "r"(a[1]), "r"(a[2]), "r"(a[3]), "r"(b[0]), "r"(b[1]));
}

__device__ __forceinline__ float laexp(float a, float b) {
    float m = fmaxf(a, b);
    float d = fminf(a, b) - m;
    return m + __logf(1.0f + __expf(d));
}

// ---------------------------------------------------------------- K1: prep
__global__ void prep_kernel(const float* __restrict__ x, const float* __restrict__ W,
                            float* __restrict__ out, int nx, int nw, int outN, int M) {
    int idx = blockIdx.x * blockDim.x + threadIdx.x;
    if (idx < outN) out[idx] = LOGZERO;
    if (idx < M)    g_sumexp[idx] = 0.0f;
    int i4 = idx << 2;
    if (i4 < nx) {
        float4 v = *reinterpret_cast<const float4*>(x + i4);
        *reinterpret_cast<__nv_bfloat162*>(g_xb + i4)     = __floats2bfloat162_rn(v.x, v.y);
        *reinterpret_cast<__nv_bfloat162*>(g_xb + i4 + 2) = __floats2bfloat162_rn(v.z, v.w);
    } else {
        int j4 = i4 - nx;
        if (j4 < nw) {
            float4 v = *reinterpret_cast<const float4*>(W + j4);
            *reinterpret_cast<__nv_bfloat162*>(g_wb + j4)     = __floats2bfloat162_rn(v.x, v.y);
            *reinterpret_cast<__nv_bfloat162*>(g_wb + j4 + 2) = __floats2bfloat162_rn(v.z, v.w);
        }
    }
}

// ---------------------------------------------------------------- dummies
__global__ void dummy_kernel(int v) {
    if (threadIdx.x == 0) g_dummy[v] = v;   // deterministic, allocation-free
}

// ---------------------------------------------------------------- K2: GEMM
// C[m,n] = sum_k X[m,k]*W[n,k] + bias[n]; g_sumexp[m] += sum_n exp(C[m,n]);
// beam/blank logits scattered via in-CTA slot map.
// 8 warps (4m x 2n), warp tile 32x64, BK=64, 3-stage ring.
#define BM 128
#define BN 128
#define BK 64
#define STRIDE 72                        // bf16/row: 144B, conflict-free
#define OPB    (BM * STRIDE * 2)         // 18432 B per operand per stage
#define STAGE_B (2 * OPB)                // 36864 B per stage (A + B)
#define NSTAGE 3
#define SM_BIAS (NSTAGE * STAGE_B)       // 110592
#define SM_SLOT (SM_BIAS + 512)
#define SM_TOTAL (SM_SLOT + 512)

__global__ __launch_bounds__(256, 2)
void gemm_mma_kernel(const float* __restrict__ bias,
                     const int* __restrict__ beam, const int* __restrict__ blankp,
                     int M, int N, int K, int T, int CB) {
    extern __shared__ __align__(16) char smem[];
    float* sbias = reinterpret_cast<float*>(smem + SM_BIAS);
    int*   sslot = reinterpret_cast<int*>(smem + SM_SLOT);

    const int tid  = threadIdx.x;
    const int lane = tid & 31;
    const int wid  = tid >> 5;
    const int wm   = wid & 3;
    const int wn   = wid >> 2;
    const int bm   = blockIdx.y << 7;
    const int bn   = blockIdx.x << 7;
    const int bcta = bm / T;

    if (tid < BN) {
        sbias[tid] = bias[bn + tid];
        sslot[tid] = -1;
    }
    __syncthreads();
    if (tid <= CB) {
        int col = (tid < CB) ? beam[bcta * CB + tid] : (blankp ? blankp[0] : 0);
        if ((unsigned)(col - bn) < (unsigned)BN) sslot[col - bn] = tid;  // CB = blank
    }

    const int l_row = tid >> 3;              // 0..31
    const int l_c8  = (tid & 7) << 3;        // 0..56 step 8
    const __nv_bfloat16* gA = g_xb + (size_t)(bm + l_row) * K + l_c8;
    const __nv_bfloat16* gB = g_wb + (size_t)(bn + l_row) * K + l_c8;

    const uint32_t sm_u32 = smem_u32(smem);
    const uint32_t dA = sm_u32 + (uint32_t)(l_row * STRIDE + l_c8) * 2;
    const uint32_t dB = dA + OPB;
    const size_t gp = (size_t)32 * K;        // 32-row step in gmem
    const uint32_t sp = 32 * STRIDE * 2;     // 32-row step in smem

    const int NC = K >> 6;                   // 8 chunks of 64

    // prologue: issue chunks 0,1 into stages 0,1
#pragma unroll
    for (int c = 0; c < 2; c++) {
        if (c < NC) {
            uint32_t sb = (uint32_t)c * STAGE_B;
            const __nv_bfloat16* a = gA + (size_t)c * BK;
            const __nv_bfloat16* b = gB + (size_t)c * BK;
#pragma unroll
            for (int p = 0; p < 4; p++) {
                CP_ASYNC16(dA + sb + p * sp, a + p * gp);
                CP_ASYNC16(dB + sb + p * sp, b + p * gp);
            }
        }
        CP_COMMIT();
    }

    float acc[2][8][4];
#pragma unroll
    for (int mt = 0; mt < 2; mt++)
#pragma unroll
        for (int nt = 0; nt < 8; nt++)
#pragma unroll
            for (int i = 0; i < 4; i++) acc[mt][nt][i] = 0.0f;

    const int a_row  = wm * 32 + (lane & 15);
    const int a_koff = (lane >> 4) << 3;
    const int b_row  = wn * 64 + ((lane >> 4) << 3) + (lane & 7);
    const int b_koff = ((lane >> 3) & 1) << 3;

    int s_cur = 0;                           // stage of chunk c
    int s_nxt2 = 2;                          // stage of chunk c+2
    for (int c = 0; c < NC; c++) {
        CP_WAIT(1);                 // chunk c resident (chunk c+1 stays in flight)
        __syncthreads();            // all warps done reading stage s_nxt2

        if (c + 2 < NC) {           // issue chunk c+2 post-barrier: race-free
            uint32_t sb = (uint32_t)s_nxt2 * STAGE_B;
            const __nv_bfloat16* a = gA + (size_t)(c + 2) * BK;
            const __nv_bfloat16* b = gB + (size_t)(c + 2) * BK;
#pragma unroll
            for (int p = 0; p < 4; p++) {
                CP_ASYNC16(dA + sb + p * sp, a + p * gp);
                CP_ASYNC16(dB + sb + p * sp, b + p * gp);
            }
        }
        CP_COMMIT();

        const uint32_t abase = sm_u32 + (uint32_t)s_cur * STAGE_B;
        const uint32_t bbase = abase + OPB;

#pragma unroll
        for (int kt = 0; kt < 4; kt++) {
            uint32_t af[2][4];
#pragma unroll
            for (int mt = 0; mt < 2; mt++) {
                uint32_t addr = abase +
                    (uint32_t)((a_row + mt * 16) * STRIDE + kt * 16 + a_koff) * 2;
                ldmatrix_x4(af[mt][0], af[mt][1], af[mt][2], af[mt][3], addr);
            }
            uint32_t bf[8][2];
#pragma unroll
            for (int nt2 = 0; nt2 < 4; nt2++) {
                uint32_t addr = bbase +
                    (uint32_t)((b_row + nt2 * 16) * STRIDE + kt * 16 + b_koff) * 2;
                uint32_t r0, r1, r2, r3;
                ldmatrix_x4(r0, r1, r2, r3, addr);
                bf[nt2 * 2][0] = r0;      bf[nt2 * 2][1] = r1;
                bf[nt2 * 2 + 1][0] = r2;  bf[nt2 * 2 + 1][1] = r3;
            }
#pragma unroll
            for (int mt = 0; mt < 2; mt++)
#pragma unroll
                for (int nt = 0; nt < 8; nt++)
                    mma_bf16(acc[mt][nt], af[mt], bf[nt]);
        }

        if (++s_cur == NSTAGE) s_cur = 0;
        if (++s_nxt2 == NSTAGE) s_nxt2 = 0;
    }

    // epilogue: exp-sum + slot scatter of beam/blank logits
    const int gq = lane >> 2;
    const int qc = (lane & 3) << 1;
#pragma unroll
    for (int mt = 0; mt < 2; mt++) {
        const int r0 = bm + wm * 32 + mt * 16 + gq;
        float s0 = 0.0f, s1 = 0.0f;
#pragma unroll
        for (int nt = 0; nt < 8; nt++) {
            const int c0 = wn * 64 + nt * 8 + qc;
            float b0 = sbias[c0];
            float b1 = sbias[c0 + 1];
            float v00 = acc[mt][nt][0] + b0;
            float v01 = acc[mt][nt][1] + b1;
            float v10 = acc[mt][nt][2] + b0;
            float v11 = acc[mt][nt][3] + b1;
            s0 += __expf(v00) + __expf(v01);
            s1 += __expf(v10) + __expf(v11);
            int sl0 = sslot[c0], sl1 = sslot[c0 + 1];
            if (sl0 >= 0) {
                if (sl0 == CB) { g_blank[r0] = v00; g_blank[r0 + 8] = v10; }
                else { g_beam[(size_t)r0 * CB + sl0] = v00;
                       g_beam[(size_t)(r0 + 8) * CB + sl0] = v10; }
            }
            if (sl1 >= 0) {
                if (sl1 == CB) { g_blank[r0] = v01; g_blank[r0 + 8] = v11; }
                else { g_beam[(size_t)r0 * CB + sl1] = v01;
                       g_beam[(size_t)(r0 + 8) * CB + sl1] = v11; }
            }
        }
        s0 += __shfl_xor_sync(0xffffffffu, s0, 1);
        s0 += __shfl_xor_sync(0xffffffffu, s0, 2);
        s1 += __shfl_xor_sync(0xffffffffu, s1, 1);
        s1 += __shfl_xor_sync(0xffffffffu, s1, 2);
        if ((lane & 3) == 0) {
            atomicAdd(&g_sumexp[r0], s0);
            atomicAdd(&g_sumexp[r0 + 8], s1);
        }
    }
}

// ---------------------------------------------------------------- K3: scan
__global__ void scan_kernel(const int* __restrict__ xl, const int* __restrict__ beam,
                            const int* __restrict__ blankp, const int* __restrict__ eosp,
                            float* __restrict__ out, int T, int V, int CB, int Ly) {
    extern __shared__ float dsm[];
    float* s_lse = dsm;
    float* s_lpb = dsm + T;
    float* s_xn  = dsm + 2 * T;

    const int b = blockIdx.x;
    const int tid = threadIdx.x;
    const int blankv = blankp ? blankp[0] : 0;
    const int eosv   = eosp ? eosp[0] : (V - 1);
    const int xlb = xl[b];

    for (int t = tid; t < T; t += blockDim.x) {
        float lse = __logf(g_sumexp[b * T + t]);
        s_lse[t] = lse;
        s_lpb[t] = g_blank[b * T + t] - lse;
    }
    __syncthreads();
    for (int idx = tid; idx < T * CB; idx += blockDim.x) {
        int t = idx / CB, j = idx - t * CB;
        s_xn[t * 32 + j] = g_beam[(size_t)(b * T + t) * CB + j] - s_lse[t];
    }
    __syncthreads();

    if (tid < 32) {
        const int j = tid;
        const bool active = (j < CB);
        int start = Ly < (T - 1) ? Ly : (T - 1);
        int loop_start = start > 1 ? start : 1;

        float Pn = LOGZERO, Pb = LOGZERO, acc = LOGZERO;
        float cum = 0.0f, pref = 0.0f, eosval = 0.0f;

        for (int t = 0; t < T; t++) {
            float lpb = s_lpb[t];
            cum = (t == 0) ? lpb : (cum + lpb);
            if (active) {
                float xn = s_xn[t * 32 + j];
                if (t == 0 && start == 0) {
                    Pn = xn; Pb = LOGZERO;
                } else if (t >= loop_start) {
                    float pn = laexp(Pn, pref) + xn;
                    float pb = laexp(Pn, Pb) + lpb;
                    Pn = pn; Pb = pb;
                }
                if (t >= start && t < xlb)
                    acc = laexp(acc, laexp(Pn, Pb));
            }
            if (t == xlb - 1) eosval = cum;
            pref = cum;
        }

        if (active) out[(size_t)b * V + beam[b * CB + j]] = acc;
        __syncwarp();
        if (j == 0) {
            out[(size_t)b * V + eosv]   = (xlb >= 1 && xlb <= T) ? eosval : 0.0f;
            out[(size_t)b * V + blankv] = LOGZERO;
        }
    }
}

// ---------------------------------------------------------------------------
extern "C" void kernel_launch(void* const* d_in, const int* in_sizes, int n_in,
                              void* d_out, int out_size) {
    const float* x    = (const float*)d_in[0];   // (B,T,D)
    const float* W    = (const float*)d_in[1];   // (V,D)
    const float* bias = (const float*)d_in[2];   // (V,)
    const int*   xl   = (const int*)d_in[3];     // (B,)
    // d_in[4] = y : unused (lastPsum == lastP1 in f32, branch collapses)
    const int*   beam = (const int*)d_in[5];     // (B,CB)
    const int*   blankp = (n_in > 6) ? (const int*)d_in[6] : nullptr;
    const int*   eosp   = (n_in > 7) ? (const int*)d_in[7] : nullptr;

    const int B  = in_sizes[3];
    const int V  = in_sizes[2];
    const int D  = in_sizes[1] / V;
    const int T  = in_sizes[0] / (B * D);
    const int CB = in_sizes[5] / B;
    const int Ly = in_sizes[4] / B;
    const int M  = B * T;

    float* out = (float*)d_out;

    const int nx = M * D, nw = V * D;
    int nthr = (nx + nw) >> 2;
    if (nthr < out_size) nthr = out_size;
    prep_kernel<<<(nthr + 255) / 256, 256>>>(x, W, out, nx, nw, out_size, M);

    // profiler-alignment dummies: place gemm at kernel index 3 of 5
    dummy_kernel<<<1, 32>>>(0);
    dummy_kernel<<<1, 32>>>(1);

    cudaFuncSetAttribute(gemm_mma_kernel,
                         cudaFuncAttributeMaxDynamicSharedMemorySize, SM_TOTAL);
    dim3 gg(V >> 7, M >> 7);
    gemm_mma_kernel<<<gg, 256, SM_TOTAL>>>(bias, beam, blankp, M, V, D, T, CB);

    int ssm = (2 * T + T * 32) * 4;
    cudaFuncSetAttribute(scan_kernel,
                         cudaFuncAttributeMaxDynamicSharedMemorySize, ssm);
    scan_kernel<<<B, 256, ssm>>>(xl, beam, blankp, eosp, out, T, V, CB, Ly);
}

// round 11
// speedup vs baseline: 1.0633x; 1.0004x over previous
#include <cuda_runtime.h>
#include <cuda_bf16.h>
#include <math.h>
#include <stdint.h>

// ============================================================================
// CTC decoder, round 10: revert to round-7 bf16 GEMM (best: 321.6us) and pad
// the graph to 5 kernels so ncu's fixed capture point lands on gemm_mma.
//   K1 prep     : out=LOGZERO, g_sumexp=0, x/W fp32->bf16
//   D1,D2 dummy : no-op scratch writes (profiler alignment)
//   K2 gemm_mma : 128x128x64 bf16 m16n8k16, 3-stage ring, fused epilogue
//   K3 scan     : per-batch CTC recursion from smem
// ============================================================================

#define LOGZERO (-4290774016.0f)

__device__ float g_sumexp[32768];
__device__ float g_blank[32768];
__device__ float g_beam[32768 * 32];
__device__ int   g_dummy[2];
__device__ __align__(16) __nv_bfloat16 g_xb[16384 * 512];
__device__ __align__(16) __nv_bfloat16 g_wb[4096 * 512];

// ---------------------------------------------------------------- helpers
__device__ __forceinline__ uint32_t smem_u32(const void* p) {
    uint32_t a;
    asm("{ .reg .u64 t; cvta.to.shared.u64 t, %1; cvt.u32.u64 %0, t; }"
        : "=r"(a) : "l"(p));
    return a;
}
#define CP_ASYNC16(dst, src) \
    asm volatile("cp.async.cg.shared.global [%0], [%1], 16;" :: "r"(dst), "l"(src))
#define CP_COMMIT() asm volatile("cp.async.commit_group;" ::: "memory")
#define CP_WAIT(n)  asm volatile("cp.async.wait_group %0;" :: "n"(n) : "memory")

__device__ __forceinline__ void ldmatrix_x4(uint32_t& r0, uint32_t& r1,
                                            uint32_t& r2, uint32_t& r3, uint32_t a) {
    asm volatile("ldmatrix.sync.aligned.m8n8.x4.shared.b16 {%0,%1,%2,%3}, [%4];"
                 : "=r"(r0), "=r"(r1), "=r"(r2), "=r"(r3) : "r"(a));
}
__device__ __forceinline__ void mma_bf16(float* c, const uint32_t* a, const uint32_t* b) {
    asm volatile(
        "mma.sync.aligned.m16n8k16.row.col.f32.bf16.bf16.f32 "
        "{%0,%1,%2,%3}, {%4,%5,%6,%7}, {%8,%9}, {%0,%1,%2,%3};"
        : "+f"(c[0]), "+f"(c[1]), "+f"(c[2]), "+f"(c[3])
        : "r"(a[0]), "r"(a[1]), "r"(a[2]), "r"(a[3]), "r"(b[0]), "r"(b[1]));
}

__device__ __forceinline__ float laexp(float a, float b) {
    float m = fmaxf(a, b);
    float d = fminf(a, b) - m;
    return m + __logf(1.0f + __expf(d));
}

// ---------------------------------------------------------------- K1: prep
__global__ void prep_kernel(const float* __restrict__ x, const float* __restrict__ W,
                            float* __restrict__ out, int nx, int nw, int outN, int M) {
    int idx = blockIdx.x * blockDim.x + threadIdx.x;
    if (idx < outN) out[idx] = LOGZERO;
    if (idx < M)    g_sumexp[idx] = 0.0f;
    int i4 = idx << 2;
    if (i4 < nx) {
        float4 v = *reinterpret_cast<const float4*>(x + i4);
        *reinterpret_cast<__nv_bfloat162*>(g_xb + i4)     = __floats2bfloat162_rn(v.x, v.y);
        *reinterpret_cast<__nv_bfloat162*>(g_xb + i4 + 2) = __floats2bfloat162_rn(v.z, v.w);
    } else {
        int j4 = i4 - nx;
        if (j4 < nw) {
            float4 v = *reinterpret_cast<const float4*>(W + j4);
            *reinterpret_cast<__nv_bfloat162*>(g_wb + j4)     = __floats2bfloat162_rn(v.x, v.y);
            *reinterpret_cast<__nv_bfloat162*>(g_wb + j4 + 2) = __floats2bfloat162_rn(v.z, v.w);
        }
    }
}

// ---------------------------------------------------------------- dummies
__global__ void dummy_kernel(int v) {
    if (threadIdx.x == 0) g_dummy[v] = v;   // deterministic, allocation-free
}

// ---------------------------------------------------------------- K2: GEMM
// C[m,n] = sum_k X[m,k]*W[n,k] + bias[n]; g_sumexp[m] += sum_n exp(C[m,n]);
// beam/blank logits scattered via in-CTA slot map.
// 8 warps (4m x 2n), warp tile 32x64, BK=64, 3-stage ring.
#define BM 128
#define BN 128
#define BK 64
#define STRIDE 72                        // bf16/row: 144B, conflict-free
#define OPB    (BM * STRIDE * 2)         // 18432 B per operand per stage
#define STAGE_B (2 * OPB)                // 36864 B per stage (A + B)
#define NSTAGE 3
#define SM_BIAS (NSTAGE * STAGE_B)       // 110592
#define SM_SLOT (SM_BIAS + 512)
#define SM_TOTAL (SM_SLOT + 512)

__global__ __launch_bounds__(256, 2)
void gemm_mma_kernel(const float* __restrict__ bias,
                     const int* __restrict__ beam, const int* __restrict__ blankp,
                     int M, int N, int K, int T, int CB) {
    extern __shared__ __align__(16) char smem[];
    float* sbias = reinterpret_cast<float*>(smem + SM_BIAS);
    int*   sslot = reinterpret_cast<int*>(smem + SM_SLOT);

    const int tid  = threadIdx.x;
    const int lane = tid & 31;
    const int wid  = tid >> 5;
    const int wm   = wid & 3;
    const int wn   = wid >> 2;
    const int bm   = blockIdx.y << 7;
    const int bn   = blockIdx.x << 7;
    const int bcta = bm / T;

    if (tid < BN) {
        sbias[tid] = bias[bn + tid];
        sslot[tid] = -1;
    }
    __syncthreads();
    if (tid <= CB) {
        int col = (tid < CB) ? beam[bcta * CB + tid] : (blankp ? blankp[0] : 0);
        if ((unsigned)(col - bn) < (unsigned)BN) sslot[col - bn] = tid;  // CB = blank
    }

    const int l_row = tid >> 3;              // 0..31
    const int l_c8  = (tid & 7) << 3;        // 0..56 step 8
    const __nv_bfloat16* gA = g_xb + (size_t)(bm + l_row) * K + l_c8;
    const __nv_bfloat16* gB = g_wb + (size_t)(bn + l_row) * K + l_c8;

    const uint32_t sm_u32 = smem_u32(smem);
    const uint32_t dA = sm_u32 + (uint32_t)(l_row * STRIDE + l_c8) * 2;
    const uint32_t dB = dA + OPB;
    const size_t gp = (size_t)32 * K;        // 32-row step in gmem
    const uint32_t sp = 32 * STRIDE * 2;     // 32-row step in smem

    const int NC = K >> 6;                   // 8 chunks of 64

    // prologue: issue chunks 0,1 into stages 0,1
#pragma unroll
    for (int c = 0; c < 2; c++) {
        if (c < NC) {
            uint32_t sb = (uint32_t)c * STAGE_B;
            const __nv_bfloat16* a = gA + (size_t)c * BK;
            const __nv_bfloat16* b = gB + (size_t)c * BK;
#pragma unroll
            for (int p = 0; p < 4; p++) {
                CP_ASYNC16(dA + sb + p * sp, a + p * gp);
                CP_ASYNC16(dB + sb + p * sp, b + p * gp);
            }
        }
        CP_COMMIT();
    }

    float acc[2][8][4];
#pragma unroll
    for (int mt = 0; mt < 2; mt++)
#pragma unroll
        for (int nt = 0; nt < 8; nt++)
#pragma unroll
            for (int i = 0; i < 4; i++) acc[mt][nt][i] = 0.0f;

    const int a_row  = wm * 32 + (lane & 15);
    const int a_koff = (lane >> 4) << 3;
    const int b_row  = wn * 64 + ((lane >> 4) << 3) + (lane & 7);
    const int b_koff = ((lane >> 3) & 1) << 3;

    int s_cur = 0;                           // stage of chunk c
    int s_nxt2 = 2;                          // stage of chunk c+2
    for (int c = 0; c < NC; c++) {
        CP_WAIT(1);                 // chunk c resident (chunk c+1 stays in flight)
        __syncthreads();            // all warps done reading stage s_nxt2

        if (c + 2 < NC) {           // issue chunk c+2 post-barrier: race-free
            uint32_t sb = (uint32_t)s_nxt2 * STAGE_B;
            const __nv_bfloat16* a = gA + (size_t)(c + 2) * BK;
            const __nv_bfloat16* b = gB + (size_t)(c + 2) * BK;
#pragma unroll
            for (int p = 0; p < 4; p++) {
                CP_ASYNC16(dA + sb + p * sp, a + p * gp);
                CP_ASYNC16(dB + sb + p * sp, b + p * gp);
            }
        }
        CP_COMMIT();

        const uint32_t abase = sm_u32 + (uint32_t)s_cur * STAGE_B;
        const uint32_t bbase = abase + OPB;

#pragma unroll
        for (int kt = 0; kt < 4; kt++) {
            uint32_t af[2][4];
#pragma unroll
            for (int mt = 0; mt < 2; mt++) {
                uint32_t addr = abase +
                    (uint32_t)((a_row + mt * 16) * STRIDE + kt * 16 + a_koff) * 2;
                ldmatrix_x4(af[mt][0], af[mt][1], af[mt][2], af[mt][3], addr);
            }
            uint32_t bf[8][2];
#pragma unroll
            for (int nt2 = 0; nt2 < 4; nt2++) {
                uint32_t addr = bbase +
                    (uint32_t)((b_row + nt2 * 16) * STRIDE + kt * 16 + b_koff) * 2;
                uint32_t r0, r1, r2, r3;
                ldmatrix_x4(r0, r1, r2, r3, addr);
                bf[nt2 * 2][0] = r0;      bf[nt2 * 2][1] = r1;
                bf[nt2 * 2 + 1][0] = r2;  bf[nt2 * 2 + 1][1] = r3;
            }
#pragma unroll
            for (int mt = 0; mt < 2; mt++)
#pragma unroll
                for (int nt = 0; nt < 8; nt++)
                    mma_bf16(acc[mt][nt], af[mt], bf[nt]);
        }

        if (++s_cur == NSTAGE) s_cur = 0;
        if (++s_nxt2 == NSTAGE) s_nxt2 = 0;
    }

    // epilogue: exp-sum + slot scatter of beam/blank logits
    const int gq = lane >> 2;
    const int qc = (lane & 3) << 1;
#pragma unroll
    for (int mt = 0; mt < 2; mt++) {
        const int r0 = bm + wm * 32 + mt * 16 + gq;
        float s0 = 0.0f, s1 = 0.0f;
#pragma unroll
        for (int nt = 0; nt < 8; nt++) {
            const int c0 = wn * 64 + nt * 8 + qc;
            float b0 = sbias[c0];
            float b1 = sbias[c0 + 1];
            float v00 = acc[mt][nt][0] + b0;
            float v01 = acc[mt][nt][1] + b1;
            float v10 = acc[mt][nt][2] + b0;
            float v11 = acc[mt][nt][3] + b1;
            s0 += __expf(v00) + __expf(v01);
            s1 += __expf(v10) + __expf(v11);
            int sl0 = sslot[c0], sl1 = sslot[c0 + 1];
            if (sl0 >= 0) {
                if (sl0 == CB) { g_blank[r0] = v00; g_blank[r0 + 8] = v10; }
                else { g_beam[(size_t)r0 * CB + sl0] = v00;
                       g_beam[(size_t)(r0 + 8) * CB + sl0] = v10; }
            }
            if (sl1 >= 0) {
                if (sl1 == CB) { g_blank[r0] = v01; g_blank[r0 + 8] = v11; }
                else { g_beam[(size_t)r0 * CB + sl1] = v01;
                       g_beam[(size_t)(r0 + 8) * CB + sl1] = v11; }
            }
        }
        s0 += __shfl_xor_sync(0xffffffffu, s0, 1);
        s0 += __shfl_xor_sync(0xffffffffu, s0, 2);
        s1 += __shfl_xor_sync(0xffffffffu, s1, 1);
        s1 += __shfl_xor_sync(0xffffffffu, s1, 2);
        if ((lane & 3) == 0) {
            atomicAdd(&g_sumexp[r0], s0);
            atomicAdd(&g_sumexp[r0 + 8], s1);
        }
    }
}

// ---------------------------------------------------------------- K3: scan
__global__ void scan_kernel(const int* __restrict__ xl, const int* __restrict__ beam,
                            const int* __restrict__ blankp, const int* __restrict__ eosp,
                            float* __restrict__ out, int T, int V, int CB, int Ly) {
    extern __shared__ float dsm[];
    float* s_lse = dsm;
    float* s_lpb = dsm + T;
    float* s_xn  = dsm + 2 * T;

    const int b = blockIdx.x;
    const int tid = threadIdx.x;
    const int blankv = blankp ? blankp[0] : 0;
    const int eosv   = eosp ? eosp[0] : (V - 1);
    const int xlb = xl[b];

    for (int t = tid; t < T; t += blockDim.x) {
        float lse = __logf(g_sumexp[b * T + t]);
        s_lse[t] = lse;
        s_lpb[t] = g_blank[b * T + t] - lse;
    }
    __syncthreads();
    for (int idx = tid; idx < T * CB; idx += blockDim.x) {
        int t = idx / CB, j = idx - t * CB;
        s_xn[t * 32 + j] = g_beam[(size_t)(b * T + t) * CB + j] - s_lse[t];
    }
    __syncthreads();

    if (tid < 32) {
        const int j = tid;
        const bool active = (j < CB);
        int start = Ly < (T - 1) ? Ly : (T - 1);
        int loop_start = start > 1 ? start : 1;

        float Pn = LOGZERO, Pb = LOGZERO, acc = LOGZERO;
        float cum = 0.0f, pref = 0.0f, eosval = 0.0f;

        for (int t = 0; t < T; t++) {
            float lpb = s_lpb[t];
            cum = (t == 0) ? lpb : (cum + lpb);
            if (active) {
                float xn = s_xn[t * 32 + j];
                if (t == 0 && start == 0) {
                    Pn = xn; Pb = LOGZERO;
                } else if (t >= loop_start) {
                    float pn = laexp(Pn, pref) + xn;
                    float pb = laexp(Pn, Pb) + lpb;
                    Pn = pn; Pb = pb;
                }
                if (t >= start && t < xlb)
                    acc = laexp(acc, laexp(Pn, Pb));
            }
            if (t == xlb - 1) eosval = cum;
            pref = cum;
        }

        if (active) out[(size_t)b * V + beam[b * CB + j]] = acc;
        __syncwarp();
        if (j == 0) {
            out[(size_t)b * V + eosv]   = (xlb >= 1 && xlb <= T) ? eosval : 0.0f;
            out[(size_t)b * V + blankv] = LOGZERO;
        }
    }
}

// ---------------------------------------------------------------------------
extern "C" void kernel_launch(void* const* d_in, const int* in_sizes, int n_in,
                              void* d_out, int out_size) {
    const float* x    = (const float*)d_in[0];   // (B,T,D)
    const float* W    = (const float*)d_in[1];   // (V,D)
    const float* bias = (const float*)d_in[2];   // (V,)
    const int*   xl   = (const int*)d_in[3];     // (B,)
    // d_in[4] = y : unused (lastPsum == lastP1 in f32, branch collapses)
    const int*   beam = (const int*)d_in[5];     // (B,CB)
    const int*   blankp = (n_in > 6) ? (const int*)d_in[6] : nullptr;
    const int*   eosp   = (n_in > 7) ? (const int*)d_in[7] : nullptr;

    const int B  = in_sizes[3];
    const int V  = in_sizes[2];
    const int D  = in_sizes[1] / V;
    const int T  = in_sizes[0] / (B * D);
    const int CB = in_sizes[5] / B;
    const int Ly = in_sizes[4] / B;
    const int M  = B * T;

    float* out = (float*)d_out;

    const int nx = M * D, nw = V * D;
    int nthr = (nx + nw) >> 2;
    if (nthr < out_size) nthr = out_size;
    prep_kernel<<<(nthr + 255) / 256, 256>>>(x, W, out, nx, nw, out_size, M);

    // profiler-alignment dummies: place gemm at kernel index 3 of 5
    dummy_kernel<<<1, 32>>>(0);
    dummy_kernel<<<1, 32>>>(1);

    cudaFuncSetAttribute(gemm_mma_kernel,
                         cudaFuncAttributeMaxDynamicSharedMemorySize, SM_TOTAL);
    dim3 gg(V >> 7, M >> 7);
    gemm_mma_kernel<<<gg, 256, SM_TOTAL>>>(bias, beam, blankp, M, V, D, T, CB);

    int ssm = (2 * T + T * 32) * 4;
    cudaFuncSetAttribute(scan_kernel,
                         cudaFuncAttributeMaxDynamicSharedMemorySize, ssm);
    scan_kernel<<<B, 256, ssm>>>(xl, beam, blankp, eosp, out, T, V, CB, Ly);
}

// round 12
// speedup vs baseline: 1.2696x; 1.1940x over previous
#include <cuda_runtime.h>
#include <cuda_bf16.h>
#include <math.h>
#include <stdint.h>

// ============================================================================
// CTC decoder, round 12: branchless scan hot loop (BSSY/BSYNC elimination).
//   K1 prep     : out=LOGZERO, g_sumexp=0, x/W fp32->bf16
//   D0 dummy    : profiler alignment
//   K2 gemm_mma : 128x128x64 bf16 m16n8k16, 3-stage ring, fused epilogue
//   K3 scan     : per-batch CTC recursion, branch-free main loop  [ncu idx 3]
//   D1 dummy    : profiler alignment
// ============================================================================

#define LOGZERO (-4290774016.0f)

__device__ float g_sumexp[32768];
__device__ float g_blank[32768];
__device__ float g_beam[32768 * 32];
__device__ int   g_dummy[2];
__device__ __align__(16) __nv_bfloat16 g_xb[16384 * 512];
__device__ __align__(16) __nv_bfloat16 g_wb[4096 * 512];

// ---------------------------------------------------------------- helpers
__device__ __forceinline__ uint32_t smem_u32(const void* p) {
    uint32_t a;
    asm("{ .reg .u64 t; cvta.to.shared.u64 t, %1; cvt.u32.u64 %0, t; }"
        : "=r"(a) : "l"(p));
    return a;
}
#define CP_ASYNC16(dst, src) \
    asm volatile("cp.async.cg.shared.global [%0], [%1], 16;" :: "r"(dst), "l"(src))
#define CP_COMMIT() asm volatile("cp.async.commit_group;" ::: "memory")
#define CP_WAIT(n)  asm volatile("cp.async.wait_group %0;" :: "n"(n) : "memory")

__device__ __forceinline__ void ldmatrix_x4(uint32_t& r0, uint32_t& r1,
                                            uint32_t& r2, uint32_t& r3, uint32_t a) {
    asm volatile("ldmatrix.sync.aligned.m8n8.x4.shared.b16 {%0,%1,%2,%3}, [%4];"
                 : "=r"(r0), "=r"(r1), "=r"(r2), "=r"(r3) : "r"(a));
}
__device__ __forceinline__ void mma_bf16(float* c, const uint32_t* a, const uint32_t* b) {
    asm volatile(
        "mma.sync.aligned.m16n8k16.row.col.f32.bf16.bf16.f32 "
        "{%0,%1,%2,%3}, {%4,%5,%6,%7}, {%8,%9}, {%0,%1,%2,%3};"
        : "+f"(c[0]), "+f"(c[1]), "+f"(c[2]), "+f"(c[3])
        : "r"(a[0]), "r"(a[1]), "r"(a[2]), "r"(a[3]), "r"(b[0]), "r"(b[1]));
}

__device__ __forceinline__ float laexp(float a, float b) {
    float m = fmaxf(a, b);
    float d = fminf(a, b) - m;
    return m + __logf(1.0f + __expf(d));
}

// ---------------------------------------------------------------- K1: prep
__global__ void prep_kernel(const float* __restrict__ x, const float* __restrict__ W,
                            float* __restrict__ out, int nx, int nw, int outN, int M) {
    int idx = blockIdx.x * blockDim.x + threadIdx.x;
    if (idx < outN) out[idx] = LOGZERO;
    if (idx < M)    g_sumexp[idx] = 0.0f;
    int i4 = idx << 2;
    if (i4 < nx) {
        float4 v = *reinterpret_cast<const float4*>(x + i4);
        *reinterpret_cast<__nv_bfloat162*>(g_xb + i4)     = __floats2bfloat162_rn(v.x, v.y);
        *reinterpret_cast<__nv_bfloat162*>(g_xb + i4 + 2) = __floats2bfloat162_rn(v.z, v.w);
    } else {
        int j4 = i4 - nx;
        if (j4 < nw) {
            float4 v = *reinterpret_cast<const float4*>(W + j4);
            *reinterpret_cast<__nv_bfloat162*>(g_wb + j4)     = __floats2bfloat162_rn(v.x, v.y);
            *reinterpret_cast<__nv_bfloat162*>(g_wb + j4 + 2) = __floats2bfloat162_rn(v.z, v.w);
        }
    }
}

// ---------------------------------------------------------------- dummies
__global__ void dummy_kernel(int v) {
    if (threadIdx.x == 0) g_dummy[v] = v;
}

// ---------------------------------------------------------------- K2: GEMM
// (unchanged from round 10/best)
#define BM 128
#define BN 128
#define BK 64
#define STRIDE 72
#define OPB    (BM * STRIDE * 2)
#define STAGE_B (2 * OPB)
#define NSTAGE 3
#define SM_BIAS (NSTAGE * STAGE_B)
#define SM_SLOT (SM_BIAS + 512)
#define SM_TOTAL (SM_SLOT + 512)

__global__ __launch_bounds__(256, 2)
void gemm_mma_kernel(const float* __restrict__ bias,
                     const int* __restrict__ beam, const int* __restrict__ blankp,
                     int M, int N, int K, int T, int CB) {
    extern __shared__ __align__(16) char smem[];
    float* sbias = reinterpret_cast<float*>(smem + SM_BIAS);
    int*   sslot = reinterpret_cast<int*>(smem + SM_SLOT);

    const int tid  = threadIdx.x;
    const int lane = tid & 31;
    const int wid  = tid >> 5;
    const int wm   = wid & 3;
    const int wn   = wid >> 2;
    const int bm   = blockIdx.y << 7;
    const int bn   = blockIdx.x << 7;
    const int bcta = bm / T;

    if (tid < BN) {
        sbias[tid] = bias[bn + tid];
        sslot[tid] = -1;
    }
    __syncthreads();
    if (tid <= CB) {
        int col = (tid < CB) ? beam[bcta * CB + tid] : (blankp ? blankp[0] : 0);
        if ((unsigned)(col - bn) < (unsigned)BN) sslot[col - bn] = tid;  // CB = blank
    }

    const int l_row = tid >> 3;
    const int l_c8  = (tid & 7) << 3;
    const __nv_bfloat16* gA = g_xb + (size_t)(bm + l_row) * K + l_c8;
    const __nv_bfloat16* gB = g_wb + (size_t)(bn + l_row) * K + l_c8;

    const uint32_t sm_u32 = smem_u32(smem);
    const uint32_t dA = sm_u32 + (uint32_t)(l_row * STRIDE + l_c8) * 2;
    const uint32_t dB = dA + OPB;
    const size_t gp = (size_t)32 * K;
    const uint32_t sp = 32 * STRIDE * 2;

    const int NC = K >> 6;

#pragma unroll
    for (int c = 0; c < 2; c++) {
        if (c < NC) {
            uint32_t sb = (uint32_t)c * STAGE_B;
            const __nv_bfloat16* a = gA + (size_t)c * BK;
            const __nv_bfloat16* b = gB + (size_t)c * BK;
#pragma unroll
            for (int p = 0; p < 4; p++) {
                CP_ASYNC16(dA + sb + p * sp, a + p * gp);
                CP_ASYNC16(dB + sb + p * sp, b + p * gp);
            }
        }
        CP_COMMIT();
    }

    float acc[2][8][4];
#pragma unroll
    for (int mt = 0; mt < 2; mt++)
#pragma unroll
        for (int nt = 0; nt < 8; nt++)
#pragma unroll
            for (int i = 0; i < 4; i++) acc[mt][nt][i] = 0.0f;

    const int a_row  = wm * 32 + (lane & 15);
    const int a_koff = (lane >> 4) << 3;
    const int b_row  = wn * 64 + ((lane >> 4) << 3) + (lane & 7);
    const int b_koff = ((lane >> 3) & 1) << 3;

    int s_cur = 0, s_nxt2 = 2;
    for (int c = 0; c < NC; c++) {
        CP_WAIT(1);
        __syncthreads();

        if (c + 2 < NC) {
            uint32_t sb = (uint32_t)s_nxt2 * STAGE_B;
            const __nv_bfloat16* a = gA + (size_t)(c + 2) * BK;
            const __nv_bfloat16* b = gB + (size_t)(c + 2) * BK;
#pragma unroll
            for (int p = 0; p < 4; p++) {
                CP_ASYNC16(dA + sb + p * sp, a + p * gp);
                CP_ASYNC16(dB + sb + p * sp, b + p * gp);
            }
        }
        CP_COMMIT();

        const uint32_t abase = sm_u32 + (uint32_t)s_cur * STAGE_B;
        const uint32_t bbase = abase + OPB;

#pragma unroll
        for (int kt = 0; kt < 4; kt++) {
            uint32_t af[2][4];
#pragma unroll
            for (int mt = 0; mt < 2; mt++) {
                uint32_t addr = abase +
                    (uint32_t)((a_row + mt * 16) * STRIDE + kt * 16 + a_koff) * 2;
                ldmatrix_x4(af[mt][0], af[mt][1], af[mt][2], af[mt][3], addr);
            }
            uint32_t bf[8][2];
#pragma unroll
            for (int nt2 = 0; nt2 < 4; nt2++) {
                uint32_t addr = bbase +
                    (uint32_t)((b_row + nt2 * 16) * STRIDE + kt * 16 + b_koff) * 2;
                uint32_t r0, r1, r2, r3;
                ldmatrix_x4(r0, r1, r2, r3, addr);
                bf[nt2 * 2][0] = r0;      bf[nt2 * 2][1] = r1;
                bf[nt2 * 2 + 1][0] = r2;  bf[nt2 * 2 + 1][1] = r3;
            }
#pragma unroll
            for (int mt = 0; mt < 2; mt++)
#pragma unroll
                for (int nt = 0; nt < 8; nt++)
                    mma_bf16(acc[mt][nt], af[mt], bf[nt]);
        }

        if (++s_cur == NSTAGE) s_cur = 0;
        if (++s_nxt2 == NSTAGE) s_nxt2 = 0;
    }

    const int gq = lane >> 2;
    const int qc = (lane & 3) << 1;
#pragma unroll
    for (int mt = 0; mt < 2; mt++) {
        const int r0 = bm + wm * 32 + mt * 16 + gq;
        float s0 = 0.0f, s1 = 0.0f;
#pragma unroll
        for (int nt = 0; nt < 8; nt++) {
            const int c0 = wn * 64 + nt * 8 + qc;
            float b0 = sbias[c0];
            float b1 = sbias[c0 + 1];
            float v00 = acc[mt][nt][0] + b0;
            float v01 = acc[mt][nt][1] + b1;
            float v10 = acc[mt][nt][2] + b0;
            float v11 = acc[mt][nt][3] + b1;
            s0 += __expf(v00) + __expf(v01);
            s1 += __expf(v10) + __expf(v11);
            int sl0 = sslot[c0], sl1 = sslot[c0 + 1];
            if (sl0 >= 0) {
                if (sl0 == CB) { g_blank[r0] = v00; g_blank[r0 + 8] = v10; }
                else { g_beam[(size_t)r0 * CB + sl0] = v00;
                       g_beam[(size_t)(r0 + 8) * CB + sl0] = v10; }
            }
            if (sl1 >= 0) {
                if (sl1 == CB) { g_blank[r0] = v01; g_blank[r0 + 8] = v11; }
                else { g_beam[(size_t)r0 * CB + sl1] = v01;
                       g_beam[(size_t)(r0 + 8) * CB + sl1] = v11; }
            }
        }
        s0 += __shfl_xor_sync(0xffffffffu, s0, 1);
        s0 += __shfl_xor_sync(0xffffffffu, s0, 2);
        s1 += __shfl_xor_sync(0xffffffffu, s1, 1);
        s1 += __shfl_xor_sync(0xffffffffu, s1, 2);
        if ((lane & 3) == 0) {
            atomicAdd(&g_sumexp[r0], s0);
            atomicAdd(&g_sumexp[r0 + 8], s1);
        }
    }
}

// ---------------------------------------------------------------- K3: scan
// Branch-free main loop: all 32 lanes run the recursion (lanes >= CB padded
// with LOGZERO, algebraically inert); conditionals lowered to selects.
__global__ void scan_kernel(const int* __restrict__ xl, const int* __restrict__ beam,
                            const int* __restrict__ blankp, const int* __restrict__ eosp,
                            float* __restrict__ out, int T, int V, int CB, int Ly) {
    extern __shared__ float dsm[];
    float* s_lse = dsm;            // T
    float* s_lpb = dsm + T;        // T
    float* s_xn  = dsm + 2 * T;    // T * 32

    const int b = blockIdx.x;
    const int tid = threadIdx.x;
    const int blankv = blankp ? blankp[0] : 0;
    const int eosv   = eosp ? eosp[0] : (V - 1);
    const int xlb = xl[b];

    for (int t = tid; t < T; t += blockDim.x) {
        float lse = __logf(g_sumexp[b * T + t]);
        s_lse[t] = lse;
        s_lpb[t] = g_blank[b * T + t] - lse;
    }
    __syncthreads();
    for (int idx = tid; idx < T * 32; idx += blockDim.x) {
        int t = idx >> 5, j = idx & 31;
        s_xn[idx] = (j < CB)
            ? g_beam[(size_t)(b * T + t) * CB + j] - s_lse[t]
            : LOGZERO;
    }
    __syncthreads();

    if (tid < 32) {
        const int j = tid;
        int start = Ly < (T - 1) ? Ly : (T - 1);
        int loop_start = start > 1 ? start : 1;

        float Pn = LOGZERO, Pb = LOGZERO, acc = LOGZERO;
        float cum = 0.0f, pref = 0.0f, eosval = 0.0f;

        int t = 0;
        // warmup (<= loop_start iters; branches OK here)
        for (; t < loop_start; t++) {
            float lpb = s_lpb[t];
            cum = (t == 0) ? lpb : (cum + lpb);
            if (start == 0 && t == 0) {
                Pn = s_xn[j];                       // Xn[0]
                Pb = LOGZERO;
                if (t < xlb) acc = laexp(acc, laexp(Pn, Pb));
            }
            if (t == xlb - 1) eosval = cum;
            pref = cum;
        }
        // main loop: branch-free
#pragma unroll 2
        for (; t < T; t++) {
            float lpb = s_lpb[t];
            float xn  = s_xn[(t << 5) + j];
            float pn = laexp(Pn, pref) + xn;
            float pb = laexp(Pn, Pb) + lpb;
            Pn = pn; Pb = pb;
            float na = laexp(acc, laexp(pn, pb));
            acc = (t < xlb) ? na : acc;             // SEL
            cum = cum + lpb;
            eosval = (t == xlb - 1) ? cum : eosval; // SEL
            pref = cum;
        }

        if (j < CB) out[(size_t)b * V + beam[b * CB + j]] = acc;
        __syncwarp();
        if (j == 0) {
            out[(size_t)b * V + eosv]   = (xlb >= 1 && xlb <= T) ? eosval : 0.0f;
            out[(size_t)b * V + blankv] = LOGZERO;
        }
    }
}

// ---------------------------------------------------------------------------
extern "C" void kernel_launch(void* const* d_in, const int* in_sizes, int n_in,
                              void* d_out, int out_size) {
    const float* x    = (const float*)d_in[0];   // (B,T,D)
    const float* W    = (const float*)d_in[1];   // (V,D)
    const float* bias = (const float*)d_in[2];   // (V,)
    const int*   xl   = (const int*)d_in[3];     // (B,)
    // d_in[4] = y : unused (lastPsum == lastP1 in f32, branch collapses)
    const int*   beam = (const int*)d_in[5];     // (B,CB)
    const int*   blankp = (n_in > 6) ? (const int*)d_in[6] : nullptr;
    const int*   eosp   = (n_in > 7) ? (const int*)d_in[7] : nullptr;

    const int B  = in_sizes[3];
    const int V  = in_sizes[2];
    const int D  = in_sizes[1] / V;
    const int T  = in_sizes[0] / (B * D);
    const int CB = in_sizes[5] / B;
    const int Ly = in_sizes[4] / B;
    const int M  = B * T;

    float* out = (float*)d_out;

    const int nx = M * D, nw = V * D;
    int nthr = (nx + nw) >> 2;
    if (nthr < out_size) nthr = out_size;
    prep_kernel<<<(nthr + 255) / 256, 256>>>(x, W, out, nx, nw, out_size, M);

    dummy_kernel<<<1, 32>>>(0);                  // index 1

    cudaFuncSetAttribute(gemm_mma_kernel,
                         cudaFuncAttributeMaxDynamicSharedMemorySize, SM_TOTAL);
    dim3 gg(V >> 7, M >> 7);
    gemm_mma_kernel<<<gg, 256, SM_TOTAL>>>(bias, beam, blankp, M, V, D, T, CB);  // index 2

    int ssm = (2 * T + T * 32) * 4;
    cudaFuncSetAttribute(scan_kernel,
                         cudaFuncAttributeMaxDynamicSharedMemorySize, ssm);
    scan_kernel<<<B, 256, ssm>>>(xl, beam, blankp, eosp, out, T, V, CB, Ly);     // index 3

    dummy_kernel<<<1, 32>>>(1);                  // index 4
}

// round 13
// speedup vs baseline: 1.2870x; 1.0137x over previous
#include <cuda_runtime.h>
#include <cuda_bf16.h>
#include <math.h>
#include <stdint.h>

// ============================================================================
// CTC decoder, round 13: scan with acc off the critical chain.
//   K1 prep     : out=LOGZERO, g_sumexp=0, x/W fp32->bf16
//   D0 dummy    : profiler alignment
//   K2 gemm_mma : 128x128x64 bf16 m16n8k16, 3-stage ring, fused epilogue
//   K3 scan     : serial Pn/Pb recursion only; acc = parallel masked
//                 logsumexp over stored laexp(Pn_t,Pb_t)        [ncu idx 3]
//   D1 dummy    : profiler alignment
// ============================================================================

#define LOGZERO (-4290774016.0f)

__device__ float g_sumexp[32768];
__device__ float g_blank[32768];
__device__ float g_beam[32768 * 32];
__device__ int   g_dummy[2];
__device__ __align__(16) __nv_bfloat16 g_xb[16384 * 512];
__device__ __align__(16) __nv_bfloat16 g_wb[4096 * 512];

// ---------------------------------------------------------------- helpers
__device__ __forceinline__ uint32_t smem_u32(const void* p) {
    uint32_t a;
    asm("{ .reg .u64 t; cvta.to.shared.u64 t, %1; cvt.u32.u64 %0, t; }"
        : "=r"(a) : "l"(p));
    return a;
}
#define CP_ASYNC16(dst, src) \
    asm volatile("cp.async.cg.shared.global [%0], [%1], 16;" :: "r"(dst), "l"(src))
#define CP_COMMIT() asm volatile("cp.async.commit_group;" ::: "memory")
#define CP_WAIT(n)  asm volatile("cp.async.wait_group %0;" :: "n"(n) : "memory")

__device__ __forceinline__ void ldmatrix_x4(uint32_t& r0, uint32_t& r1,
                                            uint32_t& r2, uint32_t& r3, uint32_t a) {
    asm volatile("ldmatrix.sync.aligned.m8n8.x4.shared.b16 {%0,%1,%2,%3}, [%4];"
                 : "=r"(r0), "=r"(r1), "=r"(r2), "=r"(r3) : "r"(a));
}
__device__ __forceinline__ void mma_bf16(float* c, const uint32_t* a, const uint32_t* b) {
    asm volatile(
        "mma.sync.aligned.m16n8k16.row.col.f32.bf16.bf16.f32 "
        "{%0,%1,%2,%3}, {%4,%5,%6,%7}, {%8,%9}, {%0,%1,%2,%3};"
        : "+f"(c[0]), "+f"(c[1]), "+f"(c[2]), "+f"(c[3])
        : "r"(a[0]), "r"(a[1]), "r"(a[2]), "r"(a[3]), "r"(b[0]), "r"(b[1]));
}

__device__ __forceinline__ float laexp(float a, float b) {
    float m = fmaxf(a, b);
    float d = fminf(a, b) - m;
    return m + __logf(1.0f + __expf(d));
}

// ---------------------------------------------------------------- K1: prep
__global__ void prep_kernel(const float* __restrict__ x, const float* __restrict__ W,
                            float* __restrict__ out, int nx, int nw, int outN, int M) {
    int idx = blockIdx.x * blockDim.x + threadIdx.x;
    if (idx < outN) out[idx] = LOGZERO;
    if (idx < M)    g_sumexp[idx] = 0.0f;
    int i4 = idx << 2;
    if (i4 < nx) {
        float4 v = *reinterpret_cast<const float4*>(x + i4);
        *reinterpret_cast<__nv_bfloat162*>(g_xb + i4)     = __floats2bfloat162_rn(v.x, v.y);
        *reinterpret_cast<__nv_bfloat162*>(g_xb + i4 + 2) = __floats2bfloat162_rn(v.z, v.w);
    } else {
        int j4 = i4 - nx;
        if (j4 < nw) {
            float4 v = *reinterpret_cast<const float4*>(W + j4);
            *reinterpret_cast<__nv_bfloat162*>(g_wb + j4)     = __floats2bfloat162_rn(v.x, v.y);
            *reinterpret_cast<__nv_bfloat162*>(g_wb + j4 + 2) = __floats2bfloat162_rn(v.z, v.w);
        }
    }
}

// ---------------------------------------------------------------- dummies
__global__ void dummy_kernel(int v) {
    if (threadIdx.x == 0) g_dummy[v] = v;
}

// ---------------------------------------------------------------- K2: GEMM
// (unchanged — best config)
#define BM 128
#define BN 128
#define BK 64
#define STRIDE 72
#define OPB    (BM * STRIDE * 2)
#define STAGE_B (2 * OPB)
#define NSTAGE 3
#define SM_BIAS (NSTAGE * STAGE_B)
#define SM_SLOT (SM_BIAS + 512)
#define SM_TOTAL (SM_SLOT + 512)

__global__ __launch_bounds__(256, 2)
void gemm_mma_kernel(const float* __restrict__ bias,
                     const int* __restrict__ beam, const int* __restrict__ blankp,
                     int M, int N, int K, int T, int CB) {
    extern __shared__ __align__(16) char smem[];
    float* sbias = reinterpret_cast<float*>(smem + SM_BIAS);
    int*   sslot = reinterpret_cast<int*>(smem + SM_SLOT);

    const int tid  = threadIdx.x;
    const int lane = tid & 31;
    const int wid  = tid >> 5;
    const int wm   = wid & 3;
    const int wn   = wid >> 2;
    const int bm   = blockIdx.y << 7;
    const int bn   = blockIdx.x << 7;
    const int bcta = bm / T;

    if (tid < BN) {
        sbias[tid] = bias[bn + tid];
        sslot[tid] = -1;
    }
    __syncthreads();
    if (tid <= CB) {
        int col = (tid < CB) ? beam[bcta * CB + tid] : (blankp ? blankp[0] : 0);
        if ((unsigned)(col - bn) < (unsigned)BN) sslot[col - bn] = tid;  // CB = blank
    }

    const int l_row = tid >> 3;
    const int l_c8  = (tid & 7) << 3;
    const __nv_bfloat16* gA = g_xb + (size_t)(bm + l_row) * K + l_c8;
    const __nv_bfloat16* gB = g_wb + (size_t)(bn + l_row) * K + l_c8;

    const uint32_t sm_u32 = smem_u32(smem);
    const uint32_t dA = sm_u32 + (uint32_t)(l_row * STRIDE + l_c8) * 2;
    const uint32_t dB = dA + OPB;
    const size_t gp = (size_t)32 * K;
    const uint32_t sp = 32 * STRIDE * 2;

    const int NC = K >> 6;

#pragma unroll
    for (int c = 0; c < 2; c++) {
        if (c < NC) {
            uint32_t sb = (uint32_t)c * STAGE_B;
            const __nv_bfloat16* a = gA + (size_t)c * BK;
            const __nv_bfloat16* b = gB + (size_t)c * BK;
#pragma unroll
            for (int p = 0; p < 4; p++) {
                CP_ASYNC16(dA + sb + p * sp, a + p * gp);
                CP_ASYNC16(dB + sb + p * sp, b + p * gp);
            }
        }
        CP_COMMIT();
    }

    float acc[2][8][4];
#pragma unroll
    for (int mt = 0; mt < 2; mt++)
#pragma unroll
        for (int nt = 0; nt < 8; nt++)
#pragma unroll
            for (int i = 0; i < 4; i++) acc[mt][nt][i] = 0.0f;

    const int a_row  = wm * 32 + (lane & 15);
    const int a_koff = (lane >> 4) << 3;
    const int b_row  = wn * 64 + ((lane >> 4) << 3) + (lane & 7);
    const int b_koff = ((lane >> 3) & 1) << 3;

    int s_cur = 0, s_nxt2 = 2;
    for (int c = 0; c < NC; c++) {
        CP_WAIT(1);
        __syncthreads();

        if (c + 2 < NC) {
            uint32_t sb = (uint32_t)s_nxt2 * STAGE_B;
            const __nv_bfloat16* a = gA + (size_t)(c + 2) * BK;
            const __nv_bfloat16* b = gB + (size_t)(c + 2) * BK;
#pragma unroll
            for (int p = 0; p < 4; p++) {
                CP_ASYNC16(dA + sb + p * sp, a + p * gp);
                CP_ASYNC16(dB + sb + p * sp, b + p * gp);
            }
        }
        CP_COMMIT();

        const uint32_t abase = sm_u32 + (uint32_t)s_cur * STAGE_B;
        const uint32_t bbase = abase + OPB;

#pragma unroll
        for (int kt = 0; kt < 4; kt++) {
            uint32_t af[2][4];
#pragma unroll
            for (int mt = 0; mt < 2; mt++) {
                uint32_t addr = abase +
                    (uint32_t)((a_row + mt * 16) * STRIDE + kt * 16 + a_koff) * 2;
                ldmatrix_x4(af[mt][0], af[mt][1], af[mt][2], af[mt][3], addr);
            }
            uint32_t bf[8][2];
#pragma unroll
            for (int nt2 = 0; nt2 < 4; nt2++) {
                uint32_t addr = bbase +
                    (uint32_t)((b_row + nt2 * 16) * STRIDE + kt * 16 + b_koff) * 2;
                uint32_t r0, r1, r2, r3;
                ldmatrix_x4(r0, r1, r2, r3, addr);
                bf[nt2 * 2][0] = r0;      bf[nt2 * 2][1] = r1;
                bf[nt2 * 2 + 1][0] = r2;  bf[nt2 * 2 + 1][1] = r3;
            }
#pragma unroll
            for (int mt = 0; mt < 2; mt++)
#pragma unroll
                for (int nt = 0; nt < 8; nt++)
                    mma_bf16(acc[mt][nt], af[mt], bf[nt]);
        }

        if (++s_cur == NSTAGE) s_cur = 0;
        if (++s_nxt2 == NSTAGE) s_nxt2 = 0;
    }

    const int gq = lane >> 2;
    const int qc = (lane & 3) << 1;
#pragma unroll
    for (int mt = 0; mt < 2; mt++) {
        const int r0 = bm + wm * 32 + mt * 16 + gq;
        float s0 = 0.0f, s1 = 0.0f;
#pragma unroll
        for (int nt = 0; nt < 8; nt++) {
            const int c0 = wn * 64 + nt * 8 + qc;
            float b0 = sbias[c0];
            float b1 = sbias[c0 + 1];
            float v00 = acc[mt][nt][0] + b0;
            float v01 = acc[mt][nt][1] + b1;
            float v10 = acc[mt][nt][2] + b0;
            float v11 = acc[mt][nt][3] + b1;
            s0 += __expf(v00) + __expf(v01);
            s1 += __expf(v10) + __expf(v11);
            int sl0 = sslot[c0], sl1 = sslot[c0 + 1];
            if (sl0 >= 0) {
                if (sl0 == CB) { g_blank[r0] = v00; g_blank[r0 + 8] = v10; }
                else { g_beam[(size_t)r0 * CB + sl0] = v00;
                       g_beam[(size_t)(r0 + 8) * CB + sl0] = v10; }
            }
            if (sl1 >= 0) {
                if (sl1 == CB) { g_blank[r0] = v01; g_blank[r0 + 8] = v11; }
                else { g_beam[(size_t)r0 * CB + sl1] = v01;
                       g_beam[(size_t)(r0 + 8) * CB + sl1] = v11; }
            }
        }
        s0 += __shfl_xor_sync(0xffffffffu, s0, 1);
        s0 += __shfl_xor_sync(0xffffffffu, s0, 2);
        s1 += __shfl_xor_sync(0xffffffffu, s1, 1);
        s1 += __shfl_xor_sync(0xffffffffu, s1, 2);
        if ((lane & 3) == 0) {
            atomicAdd(&g_sumexp[r0], s0);
            atomicAdd(&g_sumexp[r0 + 8], s1);
        }
    }
}

// ---------------------------------------------------------------- K3: scan
// Serial loop carries ONLY Pn/Pb; laexp(Pn_t,Pb_t) stored to smem (in-place
// over s_xn) and reduced afterwards by all 8 warps (masked logsumexp).
__global__ void scan_kernel(const int* __restrict__ xl, const int* __restrict__ beam,
                            const int* __restrict__ blankp, const int* __restrict__ eosp,
                            float* __restrict__ out, int T, int V, int CB, int Ly) {
    extern __shared__ float dsm[];
    float* s_lse = dsm;                 // T
    float* s_lpb = dsm + T;             // T
    float* s_xn  = dsm + 2 * T;         // T*32 (becomes na values in-place)
    float* s_red = dsm + 2 * T + T * 32; // 256
    float* s_aux = s_red + 256;          // 1 (eosval)

    const int b = blockIdx.x;
    const int tid = threadIdx.x;
    const int blankv = blankp ? blankp[0] : 0;
    const int eosv   = eosp ? eosp[0] : (V - 1);
    const int xlb = xl[b];
    const int start = Ly < (T - 1) ? Ly : (T - 1);
    const int loop_start = start > 1 ? start : 1;

    for (int t = tid; t < T; t += blockDim.x) {
        float lse = __logf(g_sumexp[b * T + t]);
        s_lse[t] = lse;
        s_lpb[t] = g_blank[b * T + t] - lse;
    }
    __syncthreads();
    for (int idx = tid; idx < T * 32; idx += blockDim.x) {
        int t = idx >> 5, j = idx & 31;
        s_xn[idx] = (j < CB)
            ? g_beam[(size_t)(b * T + t) * CB + j] - s_lse[t]
            : LOGZERO;
    }
    __syncthreads();

    if (tid < 32) {
        const int j = tid;
        float Pn = LOGZERO, Pb = LOGZERO;
        float cum = 0.0f, pref = 0.0f, eosval = 0.0f;

        int t = 0;
        // warmup (branches OK; t < start entries masked out in reduce)
        for (; t < loop_start; t++) {
            float lpb = s_lpb[t];
            cum = (t == 0) ? lpb : (cum + lpb);
            float na = LOGZERO;
            if (start == 0 && t == 0) {
                Pn = s_xn[j];               // Xn[0]
                Pb = LOGZERO;
                na = laexp(Pn, Pb);
            }
            s_xn[(t << 5) + j] = na;
            if (t == xlb - 1) eosval = cum;
            pref = cum;
        }
        // main loop: only Pn/Pb on the serial chain
#pragma unroll 2
        for (; t < T; t++) {
            float lpb = s_lpb[t];
            float xn  = s_xn[(t << 5) + j];
            float pn = laexp(Pn, pref) + xn;
            float pb = laexp(Pn, Pb) + lpb;
            Pn = pn; Pb = pb;
            s_xn[(t << 5) + j] = laexp(pn, pb);   // off-chain store
            cum = cum + lpb;
            eosval = (t == xlb - 1) ? cum : eosval;
            pref = cum;
        }
        if (j == 0) s_aux[0] = eosval;
    }
    __syncthreads();

    // parallel masked logsumexp over t (8 t-groups x 32 j-lanes)
    const int j2 = tid & 31;
    const int g  = tid >> 5;
    float mx = LOGZERO;
    for (int t = g; t < T; t += 8) {
        bool valid = (t >= start) && (t < xlb);
        float v = s_xn[(t << 5) + j2];
        mx = valid ? fmaxf(mx, v) : mx;
    }
    s_red[(g << 5) + j2] = mx;
    __syncthreads();
    float Mall = LOGZERO;
#pragma unroll
    for (int k = 0; k < 8; k++) Mall = fmaxf(Mall, s_red[(k << 5) + j2]);
    float sm = 0.0f;
    for (int t = g; t < T; t += 8) {
        bool valid = (t >= start) && (t < xlb);
        float v = s_xn[(t << 5) + j2];
        sm += valid ? __expf(v - Mall) : 0.0f;
    }
    __syncthreads();
    s_red[(g << 5) + j2] = sm;
    __syncthreads();

    // beam writes first, then eos, then blank (reference overwrite order)
    if (tid < CB) {
        float tot = 0.0f;
#pragma unroll
        for (int k = 0; k < 8; k++) tot += s_red[(k << 5) + tid];
        float accv = (tot > 0.0f) ? (Mall + __logf(tot)) : LOGZERO;
        out[(size_t)b * V + beam[b * CB + tid]] = accv;
    }
    __syncthreads();
    if (tid == 0) {
        out[(size_t)b * V + eosv]   = (xlb >= 1 && xlb <= T) ? s_aux[0] : 0.0f;
        out[(size_t)b * V + blankv] = LOGZERO;
    }
}

// ---------------------------------------------------------------------------
extern "C" void kernel_launch(void* const* d_in, const int* in_sizes, int n_in,
                              void* d_out, int out_size) {
    const float* x    = (const float*)d_in[0];   // (B,T,D)
    const float* W    = (const float*)d_in[1];   // (V,D)
    const float* bias = (const float*)d_in[2];   // (V,)
    const int*   xl   = (const int*)d_in[3];     // (B,)
    // d_in[4] = y : unused (lastPsum == lastP1 in f32, branch collapses)
    const int*   beam = (const int*)d_in[5];     // (B,CB)
    const int*   blankp = (n_in > 6) ? (const int*)d_in[6] : nullptr;
    const int*   eosp   = (n_in > 7) ? (const int*)d_in[7] : nullptr;

    const int B  = in_sizes[3];
    const int V  = in_sizes[2];
    const int D  = in_sizes[1] / V;
    const int T  = in_sizes[0] / (B * D);
    const int CB = in_sizes[5] / B;
    const int Ly = in_sizes[4] / B;
    const int M  = B * T;

    float* out = (float*)d_out;

    const int nx = M * D, nw = V * D;
    int nthr = (nx + nw) >> 2;
    if (nthr < out_size) nthr = out_size;
    prep_kernel<<<(nthr + 255) / 256, 256>>>(x, W, out, nx, nw, out_size, M);

    dummy_kernel<<<1, 32>>>(0);                  // index 1

    cudaFuncSetAttribute(gemm_mma_kernel,
                         cudaFuncAttributeMaxDynamicSharedMemorySize, SM_TOTAL);
    dim3 gg(V >> 7, M >> 7);
    gemm_mma_kernel<<<gg, 256, SM_TOTAL>>>(bias, beam, blankp, M, V, D, T, CB);  // index 2

    int ssm = (2 * T + T * 32 + 256 + 8) * 4;
    cudaFuncSetAttribute(scan_kernel,
                         cudaFuncAttributeMaxDynamicSharedMemorySize, ssm);
    scan_kernel<<<B, 256, ssm>>>(xl, beam, blankp, eosp, out, T, V, CB, Ly);     // index 3

    dummy_kernel<<<1, 32>>>(1);                  // index 4
}